// round 7
// baseline (speedup 1.0000x reference)
#include <cuda_runtime.h>
#include <cstdint>
#include <math.h>

#define Bq 4
#define Hh 16
#define Ss 4096
#define Dd 128
#define Mm 128
#define BH (Bq*Hh)
#define EPSV 1e-6f

// Scratch (no cudaMalloc allowed)
__device__ float g_S [BH*Dd*Mm];  // S_t accumulator [BH, D, M]
__device__ float g_ST[BH*Dd*Mm];  // S_t transposed  [BH, M, D] (tf32 bits)
__device__ float g_w [BH*Dd];     // w[d] = S*z_prev[d] + sum_s phi(k)[s,d]

__device__ __forceinline__ float phi(float x) {
    return x > 0.f ? x + 1.f : expf(x);
}
__device__ __forceinline__ unsigned f2tf(float x) {
    unsigned r; asm("cvt.rna.tf32.f32 %0, %1;" : "=r"(r) : "f"(x)); return r;
}
__device__ __forceinline__ unsigned s2u(const void* p) {
    unsigned a;
    asm("{ .reg .u64 t; cvta.to.shared.u64 t, %1; cvt.u32.u64 %0, t; }"
        : "=r"(a) : "l"(p));
    return a;
}
__device__ __forceinline__ void mma8(float* c, const unsigned* a, const unsigned* b) {
    asm volatile(
        "mma.sync.aligned.m16n8k8.row.col.f32.tf32.tf32.f32 "
        "{%0,%1,%2,%3}, {%4,%5,%6,%7}, {%8,%9}, {%0,%1,%2,%3};"
        : "+f"(c[0]), "+f"(c[1]), "+f"(c[2]), "+f"(c[3])
        : "r"(a[0]), "r"(a[1]), "r"(a[2]), "r"(a[3]), "r"(b[0]), "r"(b[1]));
}
__device__ __forceinline__ void ldsm4(unsigned* r, unsigned a) {
    asm volatile("ldmatrix.sync.aligned.m8n8.x4.shared.b16 {%0,%1,%2,%3}, [%4];"
        : "=r"(r[0]), "=r"(r[1]), "=r"(r[2]), "=r"(r[3]) : "r"(a));
}

// ---------------------------------------------------------------------------
// Kernel 0: init scratch
// ---------------------------------------------------------------------------
__global__ void k_init(const float* __restrict__ S_prev,
                       const float* __restrict__ z_prev) {
    int head = blockIdx.x;
    const float* sp = S_prev + (size_t)head * Dd * Mm;
    float* sg = g_S + (size_t)head * Dd * Mm;
    for (int i = threadIdx.x; i < Dd * Mm; i += blockDim.x)
        sg[i] = sp[i];
    for (int i = threadIdx.x; i < Dd; i += blockDim.x)
        g_w[head * Dd + i] = (float)Ss * z_prev[head * Dd + i];
}

// ---------------------------------------------------------------------------
// Kernel 1 (tensor, double-buffered smem, 1 sync/stage):
//   S_t += phi(k)^T v ; w += sum_s phi(k)
// grid (4, BH), 256 thr. Warp tile 32d x 64m. Staging: LDG.128 raw prefetch.
// ---------------------------------------------------------------------------
#define P1_CHUNK 1024
#define P1S 16
#define P1P 20
#define P1NST (P1_CHUNK/P1S)

__global__ void __launch_bounds__(256)
k_phase1(const float* __restrict__ kk, const float* __restrict__ vv,
         const float* __restrict__ mask) {
    __shared__ unsigned ksT[2][Dd][P1P];   // [buf][d][s]
    __shared__ unsigned vsT[2][Mm][P1P];   // [buf][m][s]

    int head = blockIdx.y;
    int sbase = blockIdx.x * P1_CHUNK;
    int tid = threadIdx.x;
    int warp = tid >> 5, lane = tid & 31;
    int gid = lane >> 2, tig = lane & 3;
    int d0w = (warp >> 1) * 32;
    int m0w = (warp & 1) * 64;
    int srow = tid & 15;          // staging: s row within stage
    int dcol = (tid >> 4) * 8;    // staging: 8-wide d/m block

    int sel = lane >> 3, lrow = lane & 7;
    unsigned aB[2], bB[2];
#pragma unroll
    for (int b = 0; b < 2; b++) {
        aB[b] = s2u(&ksT[b][0][0]) +
            (((d0w + (sel & 1) * 8 + lrow) * P1P + (sel >> 1) * 4) << 2);
        bB[b] = s2u(&vsT[b][0][0]) +
            (((m0w + (sel >> 1) * 8 + lrow) * P1P + (sel & 1) * 4) << 2);
    }

    float kacc[8];
#pragma unroll
    for (int j = 0; j < 8; j++) kacc[j] = 0.f;
    float acc[2][8][4];
#pragma unroll
    for (int ah = 0; ah < 2; ah++)
#pragma unroll
        for (int bi = 0; bi < 8; bi++)
#pragma unroll
            for (int t = 0; t < 4; t++) acc[ah][bi][t] = 0.f;

    const float* kh = kk + (size_t)head * Ss * Dd;
    const float* vh = vv + (size_t)head * Ss * Mm;
    const float* mh = mask + (size_t)head * Ss;

    float4 kA, kB, vA, vB; float mval;
    {
        int s = sbase + srow;
        kA = *(const float4*)(kh + (size_t)s * Dd + dcol);
        kB = *(const float4*)(kh + (size_t)s * Dd + dcol + 4);
        vA = *(const float4*)(vh + (size_t)s * Mm + dcol);
        vB = *(const float4*)(vh + (size_t)s * Mm + dcol + 4);
        mval = mh[s];
    }

    for (int t = 0; t < P1NST; t++) {
        int b = t & 1;
        // transform (phi/mask/tf32) + scatter-store transposed
        float kv;
        kv = phi(kA.x)*mval; kacc[0]+=kv; ksT[b][dcol+0][srow] = f2tf(kv);
        kv = phi(kA.y)*mval; kacc[1]+=kv; ksT[b][dcol+1][srow] = f2tf(kv);
        kv = phi(kA.z)*mval; kacc[2]+=kv; ksT[b][dcol+2][srow] = f2tf(kv);
        kv = phi(kA.w)*mval; kacc[3]+=kv; ksT[b][dcol+3][srow] = f2tf(kv);
        kv = phi(kB.x)*mval; kacc[4]+=kv; ksT[b][dcol+4][srow] = f2tf(kv);
        kv = phi(kB.y)*mval; kacc[5]+=kv; ksT[b][dcol+5][srow] = f2tf(kv);
        kv = phi(kB.z)*mval; kacc[6]+=kv; ksT[b][dcol+6][srow] = f2tf(kv);
        kv = phi(kB.w)*mval; kacc[7]+=kv; ksT[b][dcol+7][srow] = f2tf(kv);
        vsT[b][dcol+0][srow] = f2tf(vA.x * mval);
        vsT[b][dcol+1][srow] = f2tf(vA.y * mval);
        vsT[b][dcol+2][srow] = f2tf(vA.z * mval);
        vsT[b][dcol+3][srow] = f2tf(vA.w * mval);
        vsT[b][dcol+4][srow] = f2tf(vB.x * mval);
        vsT[b][dcol+5][srow] = f2tf(vB.y * mval);
        vsT[b][dcol+6][srow] = f2tf(vB.z * mval);
        vsT[b][dcol+7][srow] = f2tf(vB.w * mval);

        // raw prefetch next stage (latency hidden by MMA below)
        if (t + 1 < P1NST) {
            int s = sbase + (t + 1) * P1S + srow;
            kA = *(const float4*)(kh + (size_t)s * Dd + dcol);
            kB = *(const float4*)(kh + (size_t)s * Dd + dcol + 4);
            vA = *(const float4*)(vh + (size_t)s * Mm + dcol);
            vB = *(const float4*)(vh + (size_t)s * Mm + dcol + 4);
            mval = mh[s];
        }
        __syncthreads();

#pragma unroll
        for (int k8 = 0; k8 < P1S; k8 += 8) {
            unsigned A[2][4], B[4][4];
            ldsm4(A[0], aB[b] + (k8 << 2));
            ldsm4(A[1], aB[b] + ((16 * P1P + k8) << 2));
#pragma unroll
            for (int q = 0; q < 4; q++)
                ldsm4(B[q], bB[b] + ((q * 16 * P1P + k8) << 2));
#pragma unroll
            for (int ah = 0; ah < 2; ah++)
#pragma unroll
                for (int bi = 0; bi < 8; bi++)
                    mma8(acc[ah][bi], A[ah], &B[bi >> 1][(bi & 1) * 2]);
        }
    }

    float* Sg = g_S + (size_t)head * Dd * Mm;
#pragma unroll
    for (int ah = 0; ah < 2; ah++)
#pragma unroll
        for (int bi = 0; bi < 8; bi++) {
            int dr = d0w + ah * 16 + gid;
            int mc = m0w + bi * 8 + tig * 2;
            atomicAdd(&Sg[(size_t)dr * Mm + mc],       acc[ah][bi][0]);
            atomicAdd(&Sg[(size_t)dr * Mm + mc + 1],   acc[ah][bi][1]);
            atomicAdd(&Sg[(size_t)(dr+8) * Mm + mc],   acc[ah][bi][2]);
            atomicAdd(&Sg[(size_t)(dr+8) * Mm + mc+1], acc[ah][bi][3]);
        }
#pragma unroll
    for (int j = 0; j < 8; j++)
        atomicAdd(&g_w[head * Dd + dcol + j], kacc[j]);
}

// ---------------------------------------------------------------------------
// Kernel 1b: transpose S_t -> g_ST [m][d] with tf32 conversion baked in
// ---------------------------------------------------------------------------
__global__ void k_transS(void) {
    __shared__ float tile[32][33];
    int head = blockIdx.z;
    int db = blockIdx.x * 32, mb = blockIdx.y * 32;
    int tx = threadIdx.x, ty = threadIdx.y;   // 32 x 8
    const float* Sg = g_S + (size_t)head * Dd * Mm;
    float* STg = g_ST + (size_t)head * Dd * Mm;
    for (int r = ty; r < 32; r += 8)
        tile[r][tx] = Sg[(size_t)(db + r) * Mm + mb + tx];
    __syncthreads();
    for (int r = ty; r < 32; r += 8)
        STg[(size_t)(mb + r) * Dd + db + tx] =
            __uint_as_float(f2tf(tile[tx][r]));
}

// ---------------------------------------------------------------------------
// Kernel 2 (tensor, resident S_t + streamed double-buffered q):
//   out = (phi(q) @ S_t) / (phi(q).w + eps)
// grid (4, BH), 256 thr. 8 chunks of 128 s-rows; staging fused into MMA loop.
// ---------------------------------------------------------------------------
#define SQT 1024
#define NCH (SQT/128)
#define PQ 132
#define W_ST   (128*PQ)          // 16896 words
#define W_QS   (128*PQ)
#define SM2_WORDS (W_ST + 2*W_QS + 128 + 256)
#define SM2_BYTES (SM2_WORDS * 4)

__global__ void __launch_bounds__(256, 1)
k_phase2(const float* __restrict__ qq, float* __restrict__ out) {
    extern __shared__ unsigned sm2[];
    unsigned (*STs)[PQ] = (unsigned (*)[PQ])sm2;               // [m][d]
    unsigned (*qsb[2])[PQ];
    qsb[0] = (unsigned (*)[PQ])(sm2 + W_ST);
    qsb[1] = (unsigned (*)[PQ])(sm2 + W_ST + W_QS);
    float* ws   = (float*)(sm2 + W_ST + 2 * W_QS);
    float* dens = ws + 128;                                    // [2][128]

    int head = blockIdx.y;
    int sbase = blockIdx.x * SQT;
    int tid = threadIdx.x;
    int warp = tid >> 5, lane = tid & 31;
    int gid = lane >> 2, tig = lane & 3;
    int sw = (warp >> 1) * 32;
    int m0 = (warp & 1) * 64;
    int r2 = tid >> 1, dh = (tid & 1) * 64;   // staging row / d-half

    const float* qh  = qq + (size_t)head * Ss * Dd;
    const float* STg = g_ST + (size_t)head * Dd * Mm;

    // ---- prologue: load S_t tile + w ----
#pragma unroll
    for (int j = 0; j < 16; j++) {
        int idx = j * 256 + tid;           // float4 units over 128x32
        int m = idx >> 5, dq = (idx & 31) * 4;
        float4 t4 = *(const float4*)(STg + (size_t)m * Dd + dq);
        *(float4*)&STs[m][dq] = t4;
    }
    if (tid < 128) ws[tid] = g_w[head * Dd + tid];
    __syncthreads();   // ws must be visible before chunk-0 staging reads it

    // ---- stage chunk 0 ----
    {
        const float* qrow = qh + (size_t)(sbase + r2) * Dd + dh;
        float dsum = 0.f;
#pragma unroll
        for (int i = 0; i < 16; i++) {
            float4 qa = *(const float4*)(qrow + i * 4);
            float p0 = phi(qa.x), p1 = phi(qa.y), p2 = phi(qa.z), p3 = phi(qa.w);
            float4 wv = *(const float4*)(ws + dh + i * 4);
            dsum += p0 * wv.x + p1 * wv.y + p2 * wv.z + p3 * wv.w;
            uint4 st; st.x = f2tf(p0); st.y = f2tf(p1); st.z = f2tf(p2); st.w = f2tf(p3);
            *(uint4*)&qsb[0][r2][dh + i * 4] = st;
        }
        dsum += __shfl_xor_sync(0xffffffffu, dsum, 1);
        if (!(tid & 1)) dens[r2] = dsum;   // dens[0][r2]
    }

    int sel = lane >> 3, lrow = lane & 7;
    unsigned aB[2];
#pragma unroll
    for (int b = 0; b < 2; b++)
        aB[b] = s2u(qsb[b]) +
            (((sw + (sel & 1) * 8 + lrow) * PQ + (sel >> 1) * 4) << 2);
    unsigned bB = s2u(STs) +
        (((m0 + (sel >> 1) * 8 + lrow) * PQ + (sel & 1) * 4) << 2);

    for (int c = 0; c < NCH; c++) {
        int cb = c & 1, nb = cb ^ 1;
        bool more = (c + 1 < NCH);
        __syncthreads();   // qs[cb], dens[cb] ready

        float acc[2][8][4];
#pragma unroll
        for (int ah = 0; ah < 2; ah++)
#pragma unroll
            for (int bi = 0; bi < 8; bi++)
#pragma unroll
                for (int t = 0; t < 4; t++) acc[ah][bi][t] = 0.f;

        const float* qrow = qh + (size_t)(sbase + (c + 1) * 128 + r2) * Dd + dh;
        float dsum = 0.f;

#pragma unroll
        for (int i = 0; i < 16; i++) {
            int k0 = i * 8;
            // fused staging of next chunk (1 float4/thread/iter)
            if (more) {
                float4 qa = *(const float4*)(qrow + i * 4);
                float p0 = phi(qa.x), p1 = phi(qa.y), p2 = phi(qa.z), p3 = phi(qa.w);
                float4 wv = *(const float4*)(ws + dh + i * 4);
                dsum += p0 * wv.x + p1 * wv.y + p2 * wv.z + p3 * wv.w;
                uint4 st; st.x = f2tf(p0); st.y = f2tf(p1); st.z = f2tf(p2); st.w = f2tf(p3);
                *(uint4*)&qsb[nb][r2][dh + i * 4] = st;
            }
            unsigned A[2][4], B[4][4];
            ldsm4(A[0], aB[cb] + (k0 << 2));
            ldsm4(A[1], aB[cb] + ((16 * PQ + k0) << 2));
#pragma unroll
            for (int q = 0; q < 4; q++)
                ldsm4(B[q], bB + ((q * 16 * PQ + k0) << 2));
#pragma unroll
            for (int ah = 0; ah < 2; ah++)
#pragma unroll
                for (int bi = 0; bi < 8; bi++)
                    mma8(acc[ah][bi], A[ah], &B[bi >> 1][(bi & 1) * 2]);
        }
        if (more) {
            dsum += __shfl_xor_sync(0xffffffffu, dsum, 1);
            if (!(tid & 1)) dens[nb * 128 + r2] = dsum;
        }

        // epilogue for chunk c
        float* oh = out + ((size_t)head * Ss + sbase + c * 128) * Mm;
#pragma unroll
        for (int ah = 0; ah < 2; ah++) {
            int sr = sw + ah * 16 + gid;
            float inv0 = 1.f / (dens[cb * 128 + sr] + EPSV);
            float inv1 = 1.f / (dens[cb * 128 + sr + 8] + EPSV);
#pragma unroll
            for (int bi = 0; bi < 8; bi++) {
                int mc = m0 + bi * 8 + tig * 2;
                float2 r0 = make_float2(acc[ah][bi][0] * inv0, acc[ah][bi][1] * inv0);
                float2 r1 = make_float2(acc[ah][bi][2] * inv1, acc[ah][bi][3] * inv1);
                *(float2*)(oh + (size_t)sr * Mm + mc) = r0;
                *(float2*)(oh + (size_t)(sr + 8) * Mm + mc) = r1;
            }
        }
    }
}

// ---------------------------------------------------------------------------
// Kernel 3 (optional): copy S_t scratch into output region
// ---------------------------------------------------------------------------
__global__ void k_copyS(float* __restrict__ dst) {
    size_t i = (size_t)blockIdx.x * blockDim.x + threadIdx.x;
    if (i < (size_t)BH * Dd * Mm) dst[i] = g_S[i];
}

// ---------------------------------------------------------------------------
// Kernel 4 (optional): z_t[head,d,s] = z_prev[head,d] + phi(k)[head,s,d]*mask
// ---------------------------------------------------------------------------
__global__ void k_zt(const float* __restrict__ kk, const float* __restrict__ mask,
                     const float* __restrict__ z_prev, float* __restrict__ zt) {
    __shared__ float tile[32][33];
    int head = blockIdx.z;
    int s0 = blockIdx.x * 32;
    int d0 = blockIdx.y * 32;
    int tx = threadIdx.x, ty = threadIdx.y;   // 32 x 8
    const float* kh = kk + (size_t)head * Ss * Dd;
    const float* mh = mask + (size_t)head * Ss;
    for (int r = ty; r < 32; r += 8) {
        int s = s0 + r;
        tile[r][tx] = phi(kh[(size_t)s * Dd + d0 + tx]) * mh[s];
    }
    __syncthreads();
    float* zth = zt + (size_t)head * Dd * Ss;
    for (int r = ty; r < 32; r += 8) {
        int d = d0 + r;
        zth[(size_t)d * Ss + s0 + tx] = tile[tx][r] + z_prev[head * Dd + d];
    }
}

// ---------------------------------------------------------------------------
extern "C" void kernel_launch(void* const* d_in, const int* in_sizes, int n_in,
                              void* d_out, int out_size) {
    (void)in_sizes; (void)n_in;
    const float* q      = (const float*)d_in[0];
    const float* k      = (const float*)d_in[1];
    const float* v      = (const float*)d_in[2];
    const float* mask   = (const float*)d_in[3];
    const float* S_prev = (const float*)d_in[4];
    const float* z_prev = (const float*)d_in[5];
    float* out = (float*)d_out;

    cudaFuncSetAttribute(k_phase2, cudaFuncAttributeMaxDynamicSharedMemorySize,
                         SM2_BYTES);

    k_init<<<BH, 256>>>(S_prev, z_prev);

    dim3 g1(Ss / P1_CHUNK, BH);
    k_phase1<<<g1, 256>>>(k, v, mask);

    dim3 gt(Dd / 32, Mm / 32, BH);
    k_transS<<<gt, dim3(32, 8)>>>();

    dim3 g2(Ss / SQT, BH);
    k_phase2<<<g2, 256, SM2_BYTES>>>(q, out);

    const long N_OUT = (long)BH * Ss * Mm;
    const long N_ST  = (long)BH * Dd * Mm;
    const long N_ZT  = (long)BH * Dd * Ss;
    long osz = (long)out_size;
    if (osz >= N_OUT + N_ST) {
        k_copyS<<<(int)((N_ST + 255) / 256), 256>>>(out + N_OUT);
    }
    if (osz >= N_OUT + N_ST + N_ZT) {
        dim3 gz(Ss / 32, Dd / 32, BH);
        k_zt<<<gz, dim3(32, 8)>>>(k, mask, z_prev, out + N_OUT + N_ST);
    }
}

// round 8
// speedup vs baseline: 1.2784x; 1.2784x over previous
#include <cuda_runtime.h>
#include <cstdint>
#include <math.h>

#define Bq 4
#define Hh 16
#define Ss 4096
#define Dd 128
#define Mm 128
#define BH (Bq*Hh)
#define EPSV 1e-6f

__device__ float g_S [BH*Dd*Mm];  // S_t accumulator [BH, D, M]
__device__ float g_ST[BH*Dd*Mm];  // S_t transposed  [BH, M, D] (tf32 bits)
__device__ float g_w [BH*Dd];     // w[d] = S*z_prev[d] + sum_s phi(k)[s,d]

__device__ __forceinline__ float phi(float x) {
    return x > 0.f ? x + 1.f : expf(x);
}
__device__ __forceinline__ unsigned f2tf(float x) {
    unsigned r; asm("cvt.rna.tf32.f32 %0, %1;" : "=r"(r) : "f"(x)); return r;
}
__device__ __forceinline__ unsigned s2u(const void* p) {
    unsigned a;
    asm("{ .reg .u64 t; cvta.to.shared.u64 t, %1; cvt.u32.u64 %0, t; }"
        : "=r"(a) : "l"(p));
    return a;
}
__device__ __forceinline__ void mma8(float* c, const unsigned* a, const unsigned* b) {
    asm volatile(
        "mma.sync.aligned.m16n8k8.row.col.f32.tf32.tf32.f32 "
        "{%0,%1,%2,%3}, {%4,%5,%6,%7}, {%8,%9}, {%0,%1,%2,%3};"
        : "+f"(c[0]), "+f"(c[1]), "+f"(c[2]), "+f"(c[3])
        : "r"(a[0]), "r"(a[1]), "r"(a[2]), "r"(a[3]), "r"(b[0]), "r"(b[1]));
}
__device__ __forceinline__ void ldsm4(unsigned* r, unsigned a) {
    asm volatile("ldmatrix.sync.aligned.m8n8.x4.shared.b16 {%0,%1,%2,%3}, [%4];"
        : "=r"(r[0]), "=r"(r[1]), "=r"(r[2]), "=r"(r[3]) : "r"(a));
}

// ---------------------------------------------------------------------------
__global__ void k_init(const float* __restrict__ S_prev,
                       const float* __restrict__ z_prev) {
    int head = blockIdx.x;
    const float* sp = S_prev + (size_t)head * Dd * Mm;
    float* sg = g_S + (size_t)head * Dd * Mm;
    for (int i = threadIdx.x; i < Dd * Mm; i += blockDim.x)
        sg[i] = sp[i];
    for (int i = threadIdx.x; i < Dd; i += blockDim.x)
        g_w[head * Dd + i] = (float)Ss * z_prev[head * Dd + i];
}

// ---------------------------------------------------------------------------
// Kernel 1: S_t += phi(k)^T v ; w += sum_s phi(k)
// grid (8, BH) chunk 512, 256 thr, 2 CTAs/SM. Warp tile 32d x 64m.
// ---------------------------------------------------------------------------
#define P1_CHUNK 512
#define P1S 16
#define P1P 20
#define P1NST (P1_CHUNK/P1S)

__global__ void __launch_bounds__(256, 2)
k_phase1(const float* __restrict__ kk, const float* __restrict__ vv,
         const float* __restrict__ mask) {
    __shared__ unsigned ksT[2][Dd][P1P];   // [buf][d][s]
    __shared__ unsigned vsT[2][Mm][P1P];   // [buf][m][s]

    int head = blockIdx.y;
    int sbase = blockIdx.x * P1_CHUNK;
    int tid = threadIdx.x;
    int warp = tid >> 5, lane = tid & 31;
    int gid = lane >> 2, tig = lane & 3;
    int d0w = (warp >> 1) * 32;
    int m0w = (warp & 1) * 64;
    int srow = tid & 15;
    int dcol = (tid >> 4) * 8;

    int sel = lane >> 3, lrow = lane & 7;
    unsigned aB[2], bB[2];
#pragma unroll
    for (int b = 0; b < 2; b++) {
        aB[b] = s2u(&ksT[b][0][0]) +
            (((d0w + (sel & 1) * 8 + lrow) * P1P + (sel >> 1) * 4) << 2);
        bB[b] = s2u(&vsT[b][0][0]) +
            (((m0w + (sel >> 1) * 8 + lrow) * P1P + (sel & 1) * 4) << 2);
    }

    float kacc[8];
#pragma unroll
    for (int j = 0; j < 8; j++) kacc[j] = 0.f;
    float acc[2][8][4];
#pragma unroll
    for (int ah = 0; ah < 2; ah++)
#pragma unroll
        for (int bi = 0; bi < 8; bi++)
#pragma unroll
            for (int t = 0; t < 4; t++) acc[ah][bi][t] = 0.f;

    const float* kh = kk + (size_t)head * Ss * Dd;
    const float* vh = vv + (size_t)head * Ss * Mm;
    const float* mh = mask + (size_t)head * Ss;

    float4 kA, kB, vA, vB; float mval;
    {
        int s = sbase + srow;
        kA = *(const float4*)(kh + (size_t)s * Dd + dcol);
        kB = *(const float4*)(kh + (size_t)s * Dd + dcol + 4);
        vA = *(const float4*)(vh + (size_t)s * Mm + dcol);
        vB = *(const float4*)(vh + (size_t)s * Mm + dcol + 4);
        mval = mh[s];
    }

    for (int t = 0; t < P1NST; t++) {
        int b = t & 1;
        float kv;
        kv = phi(kA.x)*mval; kacc[0]+=kv; ksT[b][dcol+0][srow] = f2tf(kv);
        kv = phi(kA.y)*mval; kacc[1]+=kv; ksT[b][dcol+1][srow] = f2tf(kv);
        kv = phi(kA.z)*mval; kacc[2]+=kv; ksT[b][dcol+2][srow] = f2tf(kv);
        kv = phi(kA.w)*mval; kacc[3]+=kv; ksT[b][dcol+3][srow] = f2tf(kv);
        kv = phi(kB.x)*mval; kacc[4]+=kv; ksT[b][dcol+4][srow] = f2tf(kv);
        kv = phi(kB.y)*mval; kacc[5]+=kv; ksT[b][dcol+5][srow] = f2tf(kv);
        kv = phi(kB.z)*mval; kacc[6]+=kv; ksT[b][dcol+6][srow] = f2tf(kv);
        kv = phi(kB.w)*mval; kacc[7]+=kv; ksT[b][dcol+7][srow] = f2tf(kv);
        vsT[b][dcol+0][srow] = f2tf(vA.x * mval);
        vsT[b][dcol+1][srow] = f2tf(vA.y * mval);
        vsT[b][dcol+2][srow] = f2tf(vA.z * mval);
        vsT[b][dcol+3][srow] = f2tf(vA.w * mval);
        vsT[b][dcol+4][srow] = f2tf(vB.x * mval);
        vsT[b][dcol+5][srow] = f2tf(vB.y * mval);
        vsT[b][dcol+6][srow] = f2tf(vB.z * mval);
        vsT[b][dcol+7][srow] = f2tf(vB.w * mval);

        if (t + 1 < P1NST) {   // batched raw prefetch, hidden by MMA below
            int s = sbase + (t + 1) * P1S + srow;
            kA = *(const float4*)(kh + (size_t)s * Dd + dcol);
            kB = *(const float4*)(kh + (size_t)s * Dd + dcol + 4);
            vA = *(const float4*)(vh + (size_t)s * Mm + dcol);
            vB = *(const float4*)(vh + (size_t)s * Mm + dcol + 4);
            mval = mh[s];
        }
        __syncthreads();

#pragma unroll
        for (int k8 = 0; k8 < P1S; k8 += 8) {
            unsigned A[2][4], B[4][4];
            ldsm4(A[0], aB[b] + (k8 << 2));
            ldsm4(A[1], aB[b] + ((16 * P1P + k8) << 2));
#pragma unroll
            for (int q = 0; q < 4; q++)
                ldsm4(B[q], bB[b] + ((q * 16 * P1P + k8) << 2));
#pragma unroll
            for (int ah = 0; ah < 2; ah++)
#pragma unroll
                for (int bi = 0; bi < 8; bi++)
                    mma8(acc[ah][bi], A[ah], &B[bi >> 1][(bi & 1) * 2]);
        }
    }

    float* Sg = g_S + (size_t)head * Dd * Mm;
#pragma unroll
    for (int ah = 0; ah < 2; ah++)
#pragma unroll
        for (int bi = 0; bi < 8; bi++) {
            int dr = d0w + ah * 16 + gid;
            int mc = m0w + bi * 8 + tig * 2;
            atomicAdd(&Sg[(size_t)dr * Mm + mc],       acc[ah][bi][0]);
            atomicAdd(&Sg[(size_t)dr * Mm + mc + 1],   acc[ah][bi][1]);
            atomicAdd(&Sg[(size_t)(dr+8) * Mm + mc],   acc[ah][bi][2]);
            atomicAdd(&Sg[(size_t)(dr+8) * Mm + mc+1], acc[ah][bi][3]);
        }
    // reduce ksum across the 16 lanes sharing dcol, then 1 atomic set
#pragma unroll
    for (int j = 0; j < 8; j++) {
        kacc[j] += __shfl_xor_sync(0xffffffffu, kacc[j], 1);
        kacc[j] += __shfl_xor_sync(0xffffffffu, kacc[j], 2);
        kacc[j] += __shfl_xor_sync(0xffffffffu, kacc[j], 4);
        kacc[j] += __shfl_xor_sync(0xffffffffu, kacc[j], 8);
    }
    if ((lane & 15) == 0) {
#pragma unroll
        for (int j = 0; j < 8; j++)
            atomicAdd(&g_w[head * Dd + dcol + j], kacc[j]);
    }
}

// ---------------------------------------------------------------------------
__global__ void k_transS(void) {
    __shared__ float tile[32][33];
    int head = blockIdx.z;
    int db = blockIdx.x * 32, mb = blockIdx.y * 32;
    int tx = threadIdx.x, ty = threadIdx.y;   // 32 x 8
    const float* Sg = g_S + (size_t)head * Dd * Mm;
    float* STg = g_ST + (size_t)head * Dd * Mm;
    for (int r = ty; r < 32; r += 8)
        tile[r][tx] = Sg[(size_t)(db + r) * Mm + mb + tx];
    __syncthreads();
    for (int r = ty; r < 32; r += 8)
        STg[(size_t)(mb + r) * Dd + db + tx] =
            __uint_as_float(f2tf(tile[tx][r]));
}

// ---------------------------------------------------------------------------
// Kernel 2: out = (phi(q) @ S_t) / (phi(q).w + eps)
// grid (4, BH), 512 thr (16 warps). Resident S_t; q streamed, batched prefetch.
// ---------------------------------------------------------------------------
#define SQT 1024
#define NCH (SQT/128)
#define PQ 132
#define W_ST   (128*PQ)
#define W_QS   (128*PQ)
#define SM2_WORDS (W_ST + 2*W_QS + 128 + 256)
#define SM2_BYTES (SM2_WORDS * 4)

__global__ void __launch_bounds__(512, 1)
k_phase2(const float* __restrict__ qq, float* __restrict__ out) {
    extern __shared__ unsigned sm2[];
    unsigned (*STs)[PQ] = (unsigned (*)[PQ])sm2;               // [m][d]
    unsigned (*qsb[2])[PQ];
    qsb[0] = (unsigned (*)[PQ])(sm2 + W_ST);
    qsb[1] = (unsigned (*)[PQ])(sm2 + W_ST + W_QS);
    float* ws   = (float*)(sm2 + W_ST + 2 * W_QS);
    float* dens = ws + 128;                                    // [2][128]

    int head = blockIdx.y;
    int sbase = blockIdx.x * SQT;
    int tid = threadIdx.x;
    int warp = tid >> 5, lane = tid & 31;
    int gid = lane >> 2, tig = lane & 3;
    int sw = (warp >> 2) * 32;
    int m0 = (warp & 3) * 32;
    int r4 = tid >> 2, c4 = (tid & 3) * 4;   // staging row / word-in-16 group

    const float* qh  = qq + (size_t)head * Ss * Dd;
    const float* STg = g_ST + (size_t)head * Dd * Mm;

    // ---- prologue: resident S_t tile + w ----
#pragma unroll
    for (int i = 0; i < 8; i++) {
        float4 t4 = *(const float4*)(STg + (size_t)r4 * Dd + c4 + i * 16);
        *(float4*)&STs[r4][c4 + i * 16] = t4;
    }
    if (tid < 128) ws[tid] = g_w[head * Dd + tid];
    __syncthreads();

    // ---- stage chunk 0 (batched loads, MLP 8) ----
    {
        const float* qrow = qh + (size_t)(sbase + r4) * Dd;
        float4 qa[8];
#pragma unroll
        for (int i = 0; i < 8; i++)
            qa[i] = *(const float4*)(qrow + c4 + i * 16);
        float dsum = 0.f;
#pragma unroll
        for (int i = 0; i < 8; i++) {
            float p0 = phi(qa[i].x), p1 = phi(qa[i].y),
                  p2 = phi(qa[i].z), p3 = phi(qa[i].w);
            const float* wv = ws + c4 + i * 16;
            dsum += p0 * wv[0] + p1 * wv[1] + p2 * wv[2] + p3 * wv[3];
            uint4 st; st.x = f2tf(p0); st.y = f2tf(p1);
            st.z = f2tf(p2); st.w = f2tf(p3);
            *(uint4*)&qsb[0][r4][c4 + i * 16] = st;
        }
        dsum += __shfl_xor_sync(0xffffffffu, dsum, 1);
        dsum += __shfl_xor_sync(0xffffffffu, dsum, 2);
        if ((tid & 3) == 0) dens[r4] = dsum;
    }

    int sel = lane >> 3, lrow = lane & 7;
    unsigned aB[2];
#pragma unroll
    for (int b = 0; b < 2; b++)
        aB[b] = s2u(qsb[b]) +
            (((sw + (sel & 1) * 8 + lrow) * PQ + (sel >> 1) * 4) << 2);
    unsigned bB = s2u(STs) +
        (((m0 + (sel >> 1) * 8 + lrow) * PQ + (sel & 1) * 4) << 2);

    for (int c = 0; c < NCH; c++) {
        int cb = c & 1, nb = cb ^ 1;
        bool more = (c + 1 < NCH);

        // batched prefetch of next chunk BEFORE the sync (MLP 8)
        float4 qn[8];
        if (more) {
            const float* qrow = qh + (size_t)(sbase + (c + 1) * 128 + r4) * Dd;
#pragma unroll
            for (int i = 0; i < 8; i++)
                qn[i] = *(const float4*)(qrow + c4 + i * 16);
        }
        __syncthreads();   // qsb[cb], dens[cb] ready

        float acc[2][4][4];
#pragma unroll
        for (int ah = 0; ah < 2; ah++)
#pragma unroll
            for (int bi = 0; bi < 4; bi++)
#pragma unroll
                for (int t = 0; t < 4; t++) acc[ah][bi][t] = 0.f;
        float dsum = 0.f;

#pragma unroll
        for (int i = 0; i < 16; i++) {
            int k0 = i * 8;
            if (more && i >= 8) {   // transform+store spread over back half
                int j = i - 8;
                float p0 = phi(qn[j].x), p1 = phi(qn[j].y),
                      p2 = phi(qn[j].z), p3 = phi(qn[j].w);
                const float* wv = ws + c4 + j * 16;
                dsum += p0 * wv[0] + p1 * wv[1] + p2 * wv[2] + p3 * wv[3];
                uint4 st; st.x = f2tf(p0); st.y = f2tf(p1);
                st.z = f2tf(p2); st.w = f2tf(p3);
                *(uint4*)&qsb[nb][r4][c4 + j * 16] = st;
            }
            unsigned A[2][4], B[2][4];
            ldsm4(A[0], aB[cb] + (k0 << 2));
            ldsm4(A[1], aB[cb] + ((16 * PQ + k0) << 2));
            ldsm4(B[0], bB + (k0 << 2));
            ldsm4(B[1], bB + ((16 * PQ + k0) << 2));
#pragma unroll
            for (int ah = 0; ah < 2; ah++)
#pragma unroll
                for (int bi = 0; bi < 4; bi++)
                    mma8(acc[ah][bi], A[ah], &B[bi >> 1][(bi & 1) * 2]);
        }
        if (more) {
            dsum += __shfl_xor_sync(0xffffffffu, dsum, 1);
            dsum += __shfl_xor_sync(0xffffffffu, dsum, 2);
            if ((tid & 3) == 0) dens[nb * 128 + r4] = dsum;
        }

        // epilogue for chunk c
        float* oh = out + ((size_t)head * Ss + sbase + c * 128) * Mm;
#pragma unroll
        for (int ah = 0; ah < 2; ah++) {
            int sr = sw + ah * 16 + gid;
            float inv0 = 1.f / (dens[cb * 128 + sr] + EPSV);
            float inv1 = 1.f / (dens[cb * 128 + sr + 8] + EPSV);
#pragma unroll
            for (int bi = 0; bi < 4; bi++) {
                int mc = m0 + bi * 8 + tig * 2;
                float2 r0 = make_float2(acc[ah][bi][0] * inv0, acc[ah][bi][1] * inv0);
                float2 r1 = make_float2(acc[ah][bi][2] * inv1, acc[ah][bi][3] * inv1);
                *(float2*)(oh + (size_t)sr * Mm + mc) = r0;
                *(float2*)(oh + (size_t)(sr + 8) * Mm + mc) = r1;
            }
        }
    }
}

// ---------------------------------------------------------------------------
__global__ void k_copyS(float* __restrict__ dst) {
    size_t i = (size_t)blockIdx.x * blockDim.x + threadIdx.x;
    if (i < (size_t)BH * Dd * Mm) dst[i] = g_S[i];
}

// ---------------------------------------------------------------------------
__global__ void k_zt(const float* __restrict__ kk, const float* __restrict__ mask,
                     const float* __restrict__ z_prev, float* __restrict__ zt) {
    __shared__ float tile[32][33];
    int head = blockIdx.z;
    int s0 = blockIdx.x * 32;
    int d0 = blockIdx.y * 32;
    int tx = threadIdx.x, ty = threadIdx.y;   // 32 x 8
    const float* kh = kk + (size_t)head * Ss * Dd;
    const float* mh = mask + (size_t)head * Ss;
    for (int r = ty; r < 32; r += 8) {
        int s = s0 + r;
        tile[r][tx] = phi(kh[(size_t)s * Dd + d0 + tx]) * mh[s];
    }
    __syncthreads();
    float* zth = zt + (size_t)head * Dd * Ss;
    for (int r = ty; r < 32; r += 8) {
        int d = d0 + r;
        zth[(size_t)d * Ss + s0 + tx] = tile[tx][r] + z_prev[head * Dd + d];
    }
}

// ---------------------------------------------------------------------------
extern "C" void kernel_launch(void* const* d_in, const int* in_sizes, int n_in,
                              void* d_out, int out_size) {
    (void)in_sizes; (void)n_in;
    const float* q      = (const float*)d_in[0];
    const float* k      = (const float*)d_in[1];
    const float* v      = (const float*)d_in[2];
    const float* mask   = (const float*)d_in[3];
    const float* S_prev = (const float*)d_in[4];
    const float* z_prev = (const float*)d_in[5];
    float* out = (float*)d_out;

    cudaFuncSetAttribute(k_phase2, cudaFuncAttributeMaxDynamicSharedMemorySize,
                         SM2_BYTES);

    k_init<<<BH, 256>>>(S_prev, z_prev);

    dim3 g1(Ss / P1_CHUNK, BH);
    k_phase1<<<g1, 256>>>(k, v, mask);

    dim3 gt(Dd / 32, Mm / 32, BH);
    k_transS<<<gt, dim3(32, 8)>>>();

    dim3 g2(Ss / SQT, BH);
    k_phase2<<<g2, 512, SM2_BYTES>>>(q, out);

    const long N_OUT = (long)BH * Ss * Mm;
    const long N_ST  = (long)BH * Dd * Mm;
    const long N_ZT  = (long)BH * Dd * Ss;
    long osz = (long)out_size;
    if (osz >= N_OUT + N_ST) {
        k_copyS<<<(int)((N_ST + 255) / 256), 256>>>(out + N_OUT);
    }
    if (osz >= N_OUT + N_ST + N_ZT) {
        dim3 gz(Ss / 32, Dd / 32, BH);
        k_zt<<<gz, dim3(32, 8)>>>(k, mask, z_prev, out + N_OUT + N_ST);
    }
}

// round 9
// speedup vs baseline: 1.3999x; 1.0950x over previous
#include <cuda_runtime.h>
#include <cstdint>
#include <math.h>

#define Bq 4
#define Hh 16
#define Ss 4096
#define Dd 128
#define Mm 128
#define BH (Bq*Hh)
#define EPSV 1e-6f

__device__ float g_S [BH*Dd*Mm];  // S_t accumulator [BH, D, M]
__device__ float g_ST[BH*Dd*Mm];  // S_t transposed  [BH, M, D] (tf32 bits)
__device__ float g_w [BH*Dd];     // w[d] = S*z_prev[d] + sum_s phi(k)[s,d]

__device__ __forceinline__ float phi(float x) {
    return x > 0.f ? x + 1.f : expf(x);
}
__device__ __forceinline__ unsigned f2tf(float x) {
    unsigned r; asm("cvt.rna.tf32.f32 %0, %1;" : "=r"(r) : "f"(x)); return r;
}
__device__ __forceinline__ unsigned s2u(const void* p) {
    unsigned a;
    asm("{ .reg .u64 t; cvta.to.shared.u64 t, %1; cvt.u32.u64 %0, t; }"
        : "=r"(a) : "l"(p));
    return a;
}
__device__ __forceinline__ void mma8(float* c, const unsigned* a, const unsigned* b) {
    asm volatile(
        "mma.sync.aligned.m16n8k8.row.col.f32.tf32.tf32.f32 "
        "{%0,%1,%2,%3}, {%4,%5,%6,%7}, {%8,%9}, {%0,%1,%2,%3};"
        : "+f"(c[0]), "+f"(c[1]), "+f"(c[2]), "+f"(c[3])
        : "r"(a[0]), "r"(a[1]), "r"(a[2]), "r"(a[3]), "r"(b[0]), "r"(b[1]));
}
__device__ __forceinline__ void ldsm4(unsigned* r, unsigned a) {
    asm volatile("ldmatrix.sync.aligned.m8n8.x4.shared.b16 {%0,%1,%2,%3}, [%4];"
        : "=r"(r[0]), "=r"(r[1]), "=r"(r[2]), "=r"(r[3]) : "r"(a));
}

// ---------------------------------------------------------------------------
__global__ void k_init(const float* __restrict__ S_prev,
                       const float* __restrict__ z_prev) {
    int head = blockIdx.x;
    const float* sp = S_prev + (size_t)head * Dd * Mm;
    float* sg = g_S + (size_t)head * Dd * Mm;
    for (int i = threadIdx.x; i < Dd * Mm; i += blockDim.x)
        sg[i] = sp[i];
    for (int i = threadIdx.x; i < Dd; i += blockDim.x)
        g_w[head * Dd + i] = (float)Ss * z_prev[head * Dd + i];
}

// ---------------------------------------------------------------------------
// Kernel 1 (512 thr, 16 warps, warp tile 32d x 32m, 32-row stages, pitch 36):
//   S_t += phi(k)^T v ; w += sum_s phi(k) ; optional fused z_t write
// Staging: srow = lane (conflict-free STS.32), dgrp = warp (8 d per thread).
// ---------------------------------------------------------------------------
#define P1_CHUNK 512
#define P1S 32
#define P1P 36
#define P1NST (P1_CHUNK/P1S)          // 16
#define P1_ARR (128*P1P)              // words per [128][36] array
#define P1_SMEM_BYTES (4*P1_ARR*4)    // 73728 B

__global__ void __launch_bounds__(512, 1)
k_phase1(const float* __restrict__ kk, const float* __restrict__ vv,
         const float* __restrict__ mask, const float* __restrict__ z_prev,
         float* __restrict__ ztp) {
    extern __shared__ unsigned dyn1[];
    __shared__ float zps[Dd];

    int head = blockIdx.y;
    int sbase = blockIdx.x * P1_CHUNK;
    int tid = threadIdx.x;
    int warp = tid >> 5, lane = tid & 31;
    int gid = lane >> 2, tig = lane & 3;
    int d0w = (warp >> 2) * 32;
    int m0w = (warp & 3) * 32;
    int dbase = warp * 8;            // staging d-block of this thread

    if (tid < Dd) zps[tid] = z_prev[head * Dd + tid];

    unsigned* ksp[2] = { dyn1, dyn1 + P1_ARR };
    unsigned* vsp[2] = { dyn1 + 2 * P1_ARR, dyn1 + 3 * P1_ARR };

    int sel = lane >> 3, lrow = lane & 7;
    unsigned aB[2], bB[2];
#pragma unroll
    for (int b = 0; b < 2; b++) {
        aB[b] = s2u(ksp[b]) +
            (((d0w + (sel & 1) * 8 + lrow) * P1P + (sel >> 1) * 4) << 2);
        bB[b] = s2u(vsp[b]) +
            (((m0w + (sel >> 1) * 8 + lrow) * P1P + (sel & 1) * 4) << 2);
    }

    float kacc[8];
#pragma unroll
    for (int j = 0; j < 8; j++) kacc[j] = 0.f;
    float acc[2][4][4];
#pragma unroll
    for (int ah = 0; ah < 2; ah++)
#pragma unroll
        for (int bi = 0; bi < 4; bi++)
#pragma unroll
            for (int t = 0; t < 4; t++) acc[ah][bi][t] = 0.f;

    const float* kh = kk + (size_t)head * Ss * Dd;
    const float* vh = vv + (size_t)head * Ss * Mm;
    const float* mh = mask + (size_t)head * Ss;
    float* zth = ztp ? (ztp + (size_t)head * Dd * Ss) : (float*)0;

    float4 kA, kB, vA, vB; float mval;
    {
        int s = sbase + lane;
        kA = *(const float4*)(kh + (size_t)s * Dd + dbase);
        kB = *(const float4*)(kh + (size_t)s * Dd + dbase + 4);
        vA = *(const float4*)(vh + (size_t)s * Mm + dbase);
        vB = *(const float4*)(vh + (size_t)s * Mm + dbase + 4);
        mval = mh[s];
    }
    __syncthreads();   // zps visible

    for (int t = 0; t < P1NST; t++) {
        int b = t & 1;
        int s = sbase + t * P1S + lane;
        unsigned* kd = ksp[b] + (size_t)dbase * P1P + lane;
        unsigned* vd = vsp[b] + (size_t)dbase * P1P + lane;
        float kv0 = phi(kA.x)*mval, kv1 = phi(kA.y)*mval,
              kv2 = phi(kA.z)*mval, kv3 = phi(kA.w)*mval,
              kv4 = phi(kB.x)*mval, kv5 = phi(kB.y)*mval,
              kv6 = phi(kB.z)*mval, kv7 = phi(kB.w)*mval;
        kacc[0]+=kv0; kacc[1]+=kv1; kacc[2]+=kv2; kacc[3]+=kv3;
        kacc[4]+=kv4; kacc[5]+=kv5; kacc[6]+=kv6; kacc[7]+=kv7;
        kd[0*P1P]=f2tf(kv0); kd[1*P1P]=f2tf(kv1); kd[2*P1P]=f2tf(kv2);
        kd[3*P1P]=f2tf(kv3); kd[4*P1P]=f2tf(kv4); kd[5*P1P]=f2tf(kv5);
        kd[6*P1P]=f2tf(kv6); kd[7*P1P]=f2tf(kv7);
        vd[0*P1P]=f2tf(vA.x*mval); vd[1*P1P]=f2tf(vA.y*mval);
        vd[2*P1P]=f2tf(vA.z*mval); vd[3*P1P]=f2tf(vA.w*mval);
        vd[4*P1P]=f2tf(vB.x*mval); vd[5*P1P]=f2tf(vB.y*mval);
        vd[6*P1P]=f2tf(vB.z*mval); vd[7*P1P]=f2tf(vB.w*mval);
        if (zth) {   // fused z_t: coalesced (lanes = consecutive s)
            zth[(size_t)(dbase+0)*Ss + s] = kv0 + zps[dbase+0];
            zth[(size_t)(dbase+1)*Ss + s] = kv1 + zps[dbase+1];
            zth[(size_t)(dbase+2)*Ss + s] = kv2 + zps[dbase+2];
            zth[(size_t)(dbase+3)*Ss + s] = kv3 + zps[dbase+3];
            zth[(size_t)(dbase+4)*Ss + s] = kv4 + zps[dbase+4];
            zth[(size_t)(dbase+5)*Ss + s] = kv5 + zps[dbase+5];
            zth[(size_t)(dbase+6)*Ss + s] = kv6 + zps[dbase+6];
            zth[(size_t)(dbase+7)*Ss + s] = kv7 + zps[dbase+7];
        }

        if (t + 1 < P1NST) {   // batched raw prefetch (MLP 4), hidden by MMA
            int sn = sbase + (t + 1) * P1S + lane;
            kA = *(const float4*)(kh + (size_t)sn * Dd + dbase);
            kB = *(const float4*)(kh + (size_t)sn * Dd + dbase + 4);
            vA = *(const float4*)(vh + (size_t)sn * Mm + dbase);
            vB = *(const float4*)(vh + (size_t)sn * Mm + dbase + 4);
            mval = mh[sn];
        }
        __syncthreads();

#pragma unroll
        for (int k8 = 0; k8 < P1S; k8 += 8) {
            unsigned A[2][4], B[2][4];
            ldsm4(A[0], aB[b] + (k8 << 2));
            ldsm4(A[1], aB[b] + ((16 * P1P + k8) << 2));
            ldsm4(B[0], bB[b] + (k8 << 2));
            ldsm4(B[1], bB[b] + ((16 * P1P + k8) << 2));
#pragma unroll
            for (int ah = 0; ah < 2; ah++)
#pragma unroll
                for (int bi = 0; bi < 4; bi++)
                    mma8(acc[ah][bi], A[ah], &B[bi >> 1][(bi & 1) * 2]);
        }
    }

    float* Sg = g_S + (size_t)head * Dd * Mm;
#pragma unroll
    for (int ah = 0; ah < 2; ah++)
#pragma unroll
        for (int bi = 0; bi < 4; bi++) {
            int dr = d0w + ah * 16 + gid;
            int mc = m0w + bi * 8 + tig * 2;
            atomicAdd(&Sg[(size_t)dr * Mm + mc],       acc[ah][bi][0]);
            atomicAdd(&Sg[(size_t)dr * Mm + mc + 1],   acc[ah][bi][1]);
            atomicAdd(&Sg[(size_t)(dr+8) * Mm + mc],   acc[ah][bi][2]);
            atomicAdd(&Sg[(size_t)(dr+8) * Mm + mc+1], acc[ah][bi][3]);
        }
    // warp-reduce ksum (all 32 lanes share dbase), lane 0 atomics
#pragma unroll
    for (int j = 0; j < 8; j++) {
        kacc[j] += __shfl_xor_sync(0xffffffffu, kacc[j], 1);
        kacc[j] += __shfl_xor_sync(0xffffffffu, kacc[j], 2);
        kacc[j] += __shfl_xor_sync(0xffffffffu, kacc[j], 4);
        kacc[j] += __shfl_xor_sync(0xffffffffu, kacc[j], 8);
        kacc[j] += __shfl_xor_sync(0xffffffffu, kacc[j], 16);
    }
    if (lane == 0) {
#pragma unroll
        for (int j = 0; j < 8; j++)
            atomicAdd(&g_w[head * Dd + dbase + j], kacc[j]);
    }
}

// ---------------------------------------------------------------------------
__global__ void k_transS(void) {
    __shared__ float tile[32][33];
    int head = blockIdx.z;
    int db = blockIdx.x * 32, mb = blockIdx.y * 32;
    int tx = threadIdx.x, ty = threadIdx.y;   // 32 x 8
    const float* Sg = g_S + (size_t)head * Dd * Mm;
    float* STg = g_ST + (size_t)head * Dd * Mm;
    for (int r = ty; r < 32; r += 8)
        tile[r][tx] = Sg[(size_t)(db + r) * Mm + mb + tx];
    __syncthreads();
    for (int r = ty; r < 32; r += 8)
        STg[(size_t)(mb + r) * Dd + db + tx] =
            __uint_as_float(f2tf(tile[tx][r]));
}

// ---------------------------------------------------------------------------
// Kernel 2: out = (phi(q) @ S_t) / (phi(q).w + eps)
// grid (4, BH), 512 thr. Resident S_t; q streamed, batched prefetch.
// ---------------------------------------------------------------------------
#define SQT 1024
#define NCH (SQT/128)
#define PQ 132
#define W_ST   (128*PQ)
#define W_QS   (128*PQ)
#define SM2_WORDS (W_ST + 2*W_QS + 128 + 256)
#define SM2_BYTES (SM2_WORDS * 4)

__global__ void __launch_bounds__(512, 1)
k_phase2(const float* __restrict__ qq, float* __restrict__ out) {
    extern __shared__ unsigned sm2[];
    unsigned (*STs)[PQ] = (unsigned (*)[PQ])sm2;               // [m][d]
    unsigned (*qsb[2])[PQ];
    qsb[0] = (unsigned (*)[PQ])(sm2 + W_ST);
    qsb[1] = (unsigned (*)[PQ])(sm2 + W_ST + W_QS);
    float* ws   = (float*)(sm2 + W_ST + 2 * W_QS);
    float* dens = ws + 128;                                    // [2][128]

    int head = blockIdx.y;
    int sbase = blockIdx.x * SQT;
    int tid = threadIdx.x;
    int warp = tid >> 5, lane = tid & 31;
    int gid = lane >> 2, tig = lane & 3;
    int sw = (warp >> 2) * 32;
    int m0 = (warp & 3) * 32;
    int r4 = tid >> 2, c4 = (tid & 3) * 4;

    const float* qh  = qq + (size_t)head * Ss * Dd;
    const float* STg = g_ST + (size_t)head * Dd * Mm;

#pragma unroll
    for (int i = 0; i < 8; i++) {
        float4 t4 = *(const float4*)(STg + (size_t)r4 * Dd + c4 + i * 16);
        *(float4*)&STs[r4][c4 + i * 16] = t4;
    }
    if (tid < 128) ws[tid] = g_w[head * Dd + tid];
    __syncthreads();

    {
        const float* qrow = qh + (size_t)(sbase + r4) * Dd;
        float4 qa[8];
#pragma unroll
        for (int i = 0; i < 8; i++)
            qa[i] = *(const float4*)(qrow + c4 + i * 16);
        float dsum = 0.f;
#pragma unroll
        for (int i = 0; i < 8; i++) {
            float p0 = phi(qa[i].x), p1 = phi(qa[i].y),
                  p2 = phi(qa[i].z), p3 = phi(qa[i].w);
            const float* wv = ws + c4 + i * 16;
            dsum += p0 * wv[0] + p1 * wv[1] + p2 * wv[2] + p3 * wv[3];
            uint4 st; st.x = f2tf(p0); st.y = f2tf(p1);
            st.z = f2tf(p2); st.w = f2tf(p3);
            *(uint4*)&qsb[0][r4][c4 + i * 16] = st;
        }
        dsum += __shfl_xor_sync(0xffffffffu, dsum, 1);
        dsum += __shfl_xor_sync(0xffffffffu, dsum, 2);
        if ((tid & 3) == 0) dens[r4] = dsum;
    }

    int sel = lane >> 3, lrow = lane & 7;
    unsigned aB[2];
#pragma unroll
    for (int b = 0; b < 2; b++)
        aB[b] = s2u(qsb[b]) +
            (((sw + (sel & 1) * 8 + lrow) * PQ + (sel >> 1) * 4) << 2);
    unsigned bB = s2u(STs) +
        (((m0 + (sel >> 1) * 8 + lrow) * PQ + (sel & 1) * 4) << 2);

    for (int c = 0; c < NCH; c++) {
        int cb = c & 1, nb = cb ^ 1;
        bool more = (c + 1 < NCH);

        float4 qn[8];
        if (more) {
            const float* qrow = qh + (size_t)(sbase + (c + 1) * 128 + r4) * Dd;
#pragma unroll
            for (int i = 0; i < 8; i++)
                qn[i] = *(const float4*)(qrow + c4 + i * 16);
        }
        __syncthreads();

        float acc[2][4][4];
#pragma unroll
        for (int ah = 0; ah < 2; ah++)
#pragma unroll
            for (int bi = 0; bi < 4; bi++)
#pragma unroll
                for (int t = 0; t < 4; t++) acc[ah][bi][t] = 0.f;
        float dsum = 0.f;

#pragma unroll
        for (int i = 0; i < 16; i++) {
            int k0 = i * 8;
            if (more && i >= 8) {
                int j = i - 8;
                float p0 = phi(qn[j].x), p1 = phi(qn[j].y),
                      p2 = phi(qn[j].z), p3 = phi(qn[j].w);
                const float* wv = ws + c4 + j * 16;
                dsum += p0 * wv[0] + p1 * wv[1] + p2 * wv[2] + p3 * wv[3];
                uint4 st; st.x = f2tf(p0); st.y = f2tf(p1);
                st.z = f2tf(p2); st.w = f2tf(p3);
                *(uint4*)&qsb[nb][r4][c4 + j * 16] = st;
            }
            unsigned A[2][4], B[2][4];
            ldsm4(A[0], aB[cb] + (k0 << 2));
            ldsm4(A[1], aB[cb] + ((16 * PQ + k0) << 2));
            ldsm4(B[0], bB + (k0 << 2));
            ldsm4(B[1], bB + ((16 * PQ + k0) << 2));
#pragma unroll
            for (int ah = 0; ah < 2; ah++)
#pragma unroll
                for (int bi = 0; bi < 4; bi++)
                    mma8(acc[ah][bi], A[ah], &B[bi >> 1][(bi & 1) * 2]);
        }
        if (more) {
            dsum += __shfl_xor_sync(0xffffffffu, dsum, 1);
            dsum += __shfl_xor_sync(0xffffffffu, dsum, 2);
            if ((tid & 3) == 0) dens[nb * 128 + r4] = dsum;
        }

        float* oh = out + ((size_t)head * Ss + sbase + c * 128) * Mm;
#pragma unroll
        for (int ah = 0; ah < 2; ah++) {
            int sr = sw + ah * 16 + gid;
            float inv0 = 1.f / (dens[cb * 128 + sr] + EPSV);
            float inv1 = 1.f / (dens[cb * 128 + sr + 8] + EPSV);
#pragma unroll
            for (int bi = 0; bi < 4; bi++) {
                int mc = m0 + bi * 8 + tig * 2;
                float2 r0 = make_float2(acc[ah][bi][0] * inv0, acc[ah][bi][1] * inv0);
                float2 r1 = make_float2(acc[ah][bi][2] * inv1, acc[ah][bi][3] * inv1);
                *(float2*)(oh + (size_t)sr * Mm + mc) = r0;
                *(float2*)(oh + (size_t)(sr + 8) * Mm + mc) = r1;
            }
        }
    }
}

// ---------------------------------------------------------------------------
__global__ void k_copyS(float* __restrict__ dst) {
    size_t i = (size_t)blockIdx.x * blockDim.x + threadIdx.x;
    if (i < (size_t)BH * Dd * Mm) dst[i] = g_S[i];
}

// ---------------------------------------------------------------------------
extern "C" void kernel_launch(void* const* d_in, const int* in_sizes, int n_in,
                              void* d_out, int out_size) {
    (void)in_sizes; (void)n_in;
    const float* q      = (const float*)d_in[0];
    const float* k      = (const float*)d_in[1];
    const float* v      = (const float*)d_in[2];
    const float* mask   = (const float*)d_in[3];
    const float* S_prev = (const float*)d_in[4];
    const float* z_prev = (const float*)d_in[5];
    float* out = (float*)d_out;

    cudaFuncSetAttribute(k_phase1, cudaFuncAttributeMaxDynamicSharedMemorySize,
                         P1_SMEM_BYTES);
    cudaFuncSetAttribute(k_phase2, cudaFuncAttributeMaxDynamicSharedMemorySize,
                         SM2_BYTES);

    const long N_OUT = (long)BH * Ss * Mm;
    const long N_ST  = (long)BH * Dd * Mm;
    const long N_ZT  = (long)BH * Dd * Ss;
    long osz = (long)out_size;
    float* ztp = (osz >= N_OUT + N_ST + N_ZT) ? (out + N_OUT + N_ST) : (float*)0;

    k_init<<<BH, 256>>>(S_prev, z_prev);

    dim3 g1(Ss / P1_CHUNK, BH);
    k_phase1<<<g1, 512, P1_SMEM_BYTES>>>(k, v, mask, z_prev, ztp);

    dim3 gt(Dd / 32, Mm / 32, BH);
    k_transS<<<gt, dim3(32, 8)>>>();

    dim3 g2(Ss / SQT, BH);
    k_phase2<<<g2, 512, SM2_BYTES>>>(q, out);

    if (osz >= N_OUT + N_ST) {
        k_copyS<<<(int)((N_ST + 255) / 256), 256>>>(out + N_OUT);
    }
}

// round 10
// speedup vs baseline: 1.6215x; 1.1583x over previous
#include <cuda_runtime.h>
#include <cstdint>
#include <math.h>

#define Bq 4
#define Hh 16
#define Ss 4096
#define Dd 128
#define Mm 128
#define BH (Bq*Hh)
#define EPSV 1e-6f

// Scratch (zero at first load; every execution re-zeroes g_S/g_w in k_transS)
__device__ float g_S [BH*Dd*Mm];  // S accumulation (WITHOUT S_prev), zero-based
__device__ float g_ST[BH*Dd*Mm];  // S_t transposed [BH, M, D] (tf32 bits)
__device__ float g_w [BH*Dd];     // sum_s phi(k)[s,d] accumulation, zero-based
__device__ float g_w2[BH*Dd];     // final w[d] = Ss*z_prev[d] + g_w[d]

__device__ __forceinline__ float phi(float x) {
    return x > 0.f ? x + 1.f : expf(x);
}
__device__ __forceinline__ unsigned f2tf(float x) {
    unsigned r; asm("cvt.rna.tf32.f32 %0, %1;" : "=r"(r) : "f"(x)); return r;
}
__device__ __forceinline__ unsigned s2u(const void* p) {
    unsigned a;
    asm("{ .reg .u64 t; cvta.to.shared.u64 t, %1; cvt.u32.u64 %0, t; }"
        : "=r"(a) : "l"(p));
    return a;
}
__device__ __forceinline__ void mma8(float* c, const unsigned* a, const unsigned* b) {
    asm volatile(
        "mma.sync.aligned.m16n8k8.row.col.f32.tf32.tf32.f32 "
        "{%0,%1,%2,%3}, {%4,%5,%6,%7}, {%8,%9}, {%0,%1,%2,%3};"
        : "+f"(c[0]), "+f"(c[1]), "+f"(c[2]), "+f"(c[3])
        : "r"(a[0]), "r"(a[1]), "r"(a[2]), "r"(a[3]), "r"(b[0]), "r"(b[1]));
}
__device__ __forceinline__ void ldsm4(unsigned* r, unsigned a) {
    asm volatile("ldmatrix.sync.aligned.m8n8.x4.shared.b16 {%0,%1,%2,%3}, [%4];"
        : "=r"(r[0]), "=r"(r[1]), "=r"(r[2]), "=r"(r[3]) : "r"(a));
}

// ---------------------------------------------------------------------------
// Kernel 1 (512 thr, warp tile 32d x 32m, 32-row stages, pitch 36):
//   g_S += phi(k)^T v ; g_w += sum_s phi(k) ; optional fused z_t write
// ---------------------------------------------------------------------------
#define P1_CHUNK 512
#define P1S 32
#define P1P 36
#define P1NST (P1_CHUNK/P1S)          // 16
#define P1_ARR (128*P1P)
#define P1_SMEM_BYTES (4*P1_ARR*4)    // 73728 B

__global__ void __launch_bounds__(512, 1)
k_phase1(const float* __restrict__ kk, const float* __restrict__ vv,
         const float* __restrict__ mask, const float* __restrict__ z_prev,
         float* __restrict__ ztp) {
    extern __shared__ unsigned dyn1[];
    __shared__ float zps[Dd];

    int head = blockIdx.y;
    int sbase = blockIdx.x * P1_CHUNK;
    int tid = threadIdx.x;
    int warp = tid >> 5, lane = tid & 31;
    int gid = lane >> 2, tig = lane & 3;
    int d0w = (warp >> 2) * 32;
    int m0w = (warp & 3) * 32;
    int dbase = warp * 8;

    if (tid < Dd) zps[tid] = z_prev[head * Dd + tid];

    unsigned* ksp[2] = { dyn1, dyn1 + P1_ARR };
    unsigned* vsp[2] = { dyn1 + 2 * P1_ARR, dyn1 + 3 * P1_ARR };

    int sel = lane >> 3, lrow = lane & 7;
    unsigned aB[2], bB[2];
#pragma unroll
    for (int b = 0; b < 2; b++) {
        aB[b] = s2u(ksp[b]) +
            (((d0w + (sel & 1) * 8 + lrow) * P1P + (sel >> 1) * 4) << 2);
        bB[b] = s2u(vsp[b]) +
            (((m0w + (sel >> 1) * 8 + lrow) * P1P + (sel & 1) * 4) << 2);
    }

    float kacc[8];
#pragma unroll
    for (int j = 0; j < 8; j++) kacc[j] = 0.f;
    float acc[2][4][4];
#pragma unroll
    for (int ah = 0; ah < 2; ah++)
#pragma unroll
        for (int bi = 0; bi < 4; bi++)
#pragma unroll
            for (int t = 0; t < 4; t++) acc[ah][bi][t] = 0.f;

    const float* kh = kk + (size_t)head * Ss * Dd;
    const float* vh = vv + (size_t)head * Ss * Mm;
    const float* mh = mask + (size_t)head * Ss;
    float* zth = ztp ? (ztp + (size_t)head * Dd * Ss) : (float*)0;

    float4 kA, kB, vA, vB; float mval;
    {
        int s = sbase + lane;
        kA = *(const float4*)(kh + (size_t)s * Dd + dbase);
        kB = *(const float4*)(kh + (size_t)s * Dd + dbase + 4);
        vA = *(const float4*)(vh + (size_t)s * Mm + dbase);
        vB = *(const float4*)(vh + (size_t)s * Mm + dbase + 4);
        mval = mh[s];
    }
    __syncthreads();   // zps visible

    for (int t = 0; t < P1NST; t++) {
        int b = t & 1;
        int s = sbase + t * P1S + lane;
        unsigned* kd = ksp[b] + (size_t)dbase * P1P + lane;
        unsigned* vd = vsp[b] + (size_t)dbase * P1P + lane;
        float kv0 = phi(kA.x)*mval, kv1 = phi(kA.y)*mval,
              kv2 = phi(kA.z)*mval, kv3 = phi(kA.w)*mval,
              kv4 = phi(kB.x)*mval, kv5 = phi(kB.y)*mval,
              kv6 = phi(kB.z)*mval, kv7 = phi(kB.w)*mval;
        kacc[0]+=kv0; kacc[1]+=kv1; kacc[2]+=kv2; kacc[3]+=kv3;
        kacc[4]+=kv4; kacc[5]+=kv5; kacc[6]+=kv6; kacc[7]+=kv7;
        kd[0*P1P]=f2tf(kv0); kd[1*P1P]=f2tf(kv1); kd[2*P1P]=f2tf(kv2);
        kd[3*P1P]=f2tf(kv3); kd[4*P1P]=f2tf(kv4); kd[5*P1P]=f2tf(kv5);
        kd[6*P1P]=f2tf(kv6); kd[7*P1P]=f2tf(kv7);
        float v0=vA.x*mval, v1=vA.y*mval, v2=vA.z*mval, v3=vA.w*mval,
              v4=vB.x*mval, v5=vB.y*mval, v6=vB.z*mval, v7=vB.w*mval;
        vd[0*P1P]=f2tf(v0); vd[1*P1P]=f2tf(v1); vd[2*P1P]=f2tf(v2);
        vd[3*P1P]=f2tf(v3); vd[4*P1P]=f2tf(v4); vd[5*P1P]=f2tf(v5);
        vd[6*P1P]=f2tf(v6); vd[7*P1P]=f2tf(v7);

        if (t + 1 < P1NST) {   // batched raw prefetch, hidden by MMA below
            int sn = sbase + (t + 1) * P1S + lane;
            kA = *(const float4*)(kh + (size_t)sn * Dd + dbase);
            kB = *(const float4*)(kh + (size_t)sn * Dd + dbase + 4);
            vA = *(const float4*)(vh + (size_t)sn * Mm + dbase);
            vB = *(const float4*)(vh + (size_t)sn * Mm + dbase + 4);
            mval = mh[sn];
        }
        if (zth) {   // fused z_t: coalesced (lanes = consecutive s)
            zth[(size_t)(dbase+0)*Ss + s] = kv0 + zps[dbase+0];
            zth[(size_t)(dbase+1)*Ss + s] = kv1 + zps[dbase+1];
            zth[(size_t)(dbase+2)*Ss + s] = kv2 + zps[dbase+2];
            zth[(size_t)(dbase+3)*Ss + s] = kv3 + zps[dbase+3];
            zth[(size_t)(dbase+4)*Ss + s] = kv4 + zps[dbase+4];
            zth[(size_t)(dbase+5)*Ss + s] = kv5 + zps[dbase+5];
            zth[(size_t)(dbase+6)*Ss + s] = kv6 + zps[dbase+6];
            zth[(size_t)(dbase+7)*Ss + s] = kv7 + zps[dbase+7];
        }
        __syncthreads();

#pragma unroll
        for (int k8 = 0; k8 < P1S; k8 += 8) {
            unsigned A[2][4], B[2][4];
            ldsm4(A[0], aB[b] + (k8 << 2));
            ldsm4(A[1], aB[b] + ((16 * P1P + k8) << 2));
            ldsm4(B[0], bB[b] + (k8 << 2));
            ldsm4(B[1], bB[b] + ((16 * P1P + k8) << 2));
#pragma unroll
            for (int ah = 0; ah < 2; ah++)
#pragma unroll
                for (int bi = 0; bi < 4; bi++)
                    mma8(acc[ah][bi], A[ah], &B[bi >> 1][(bi & 1) * 2]);
        }
    }

    float* Sg = g_S + (size_t)head * Dd * Mm;
#pragma unroll
    for (int ah = 0; ah < 2; ah++)
#pragma unroll
        for (int bi = 0; bi < 4; bi++) {
            int dr = d0w + ah * 16 + gid;
            int mc = m0w + bi * 8 + tig * 2;
            atomicAdd(&Sg[(size_t)dr * Mm + mc],       acc[ah][bi][0]);
            atomicAdd(&Sg[(size_t)dr * Mm + mc + 1],   acc[ah][bi][1]);
            atomicAdd(&Sg[(size_t)(dr+8) * Mm + mc],   acc[ah][bi][2]);
            atomicAdd(&Sg[(size_t)(dr+8) * Mm + mc+1], acc[ah][bi][3]);
        }
#pragma unroll
    for (int j = 0; j < 8; j++) {
        kacc[j] += __shfl_xor_sync(0xffffffffu, kacc[j], 1);
        kacc[j] += __shfl_xor_sync(0xffffffffu, kacc[j], 2);
        kacc[j] += __shfl_xor_sync(0xffffffffu, kacc[j], 4);
        kacc[j] += __shfl_xor_sync(0xffffffffu, kacc[j], 8);
        kacc[j] += __shfl_xor_sync(0xffffffffu, kacc[j], 16);
    }
    if (lane == 0) {
#pragma unroll
        for (int j = 0; j < 8; j++)
            atomicAdd(&g_w[head * Dd + dbase + j], kacc[j]);
    }
}

// ---------------------------------------------------------------------------
// Kernel 1b (fused): S_t = g_S + S_prev -> (outS copy, g_ST transposed tf32),
// g_w2 = g_w + Ss*z_prev; re-zero g_S and g_w for next graph replay.
// ---------------------------------------------------------------------------
__global__ void k_transS(const float* __restrict__ S_prev,
                         const float* __restrict__ z_prev,
                         float* __restrict__ outS) {
    __shared__ float tile[32][33];
    int head = blockIdx.z;
    int db = blockIdx.x * 32, mb = blockIdx.y * 32;
    int tx = threadIdx.x, ty = threadIdx.y;   // 32 x 8
    float* Sg = g_S + (size_t)head * Dd * Mm;
    const float* Sp = S_prev + (size_t)head * Dd * Mm;
    float* STg = g_ST + (size_t)head * Dd * Mm;
    float* So = outS ? (outS + (size_t)head * Dd * Mm) : (float*)0;
    for (int r = ty; r < 32; r += 8) {
        size_t idx = (size_t)(db + r) * Mm + mb + tx;
        float val = Sg[idx] + Sp[idx];
        tile[r][tx] = val;
        if (So) So[idx] = val;
        Sg[idx] = 0.f;                       // reset for next replay
    }
    if (blockIdx.x == 0 && blockIdx.y == 0) {
        int tid = ty * 32 + tx;
        if (tid < Dd) {
            g_w2[head * Dd + tid] = g_w[head * Dd + tid]
                                  + (float)Ss * z_prev[head * Dd + tid];
            g_w[head * Dd + tid] = 0.f;      // reset for next replay
        }
    }
    __syncthreads();
    for (int r = ty; r < 32; r += 8)
        STg[(size_t)(mb + r) * Dd + db + tx] =
            __uint_as_float(f2tf(tile[tx][r]));
}

// ---------------------------------------------------------------------------
// Kernel 2: out = (phi(q) @ S_t) / (phi(q).w + eps)
// grid (2, BH) = 128 CTAs (single wave), 512 thr. Resident S_t; q streamed.
// ---------------------------------------------------------------------------
#define SQT 2048
#define NCH (SQT/128)
#define PQ 132
#define W_ST   (128*PQ)
#define W_QS   (128*PQ)
#define SM2_WORDS (W_ST + 2*W_QS + 128 + 256)
#define SM2_BYTES (SM2_WORDS * 4)

__global__ void __launch_bounds__(512, 1)
k_phase2(const float* __restrict__ qq, float* __restrict__ out) {
    extern __shared__ unsigned sm2[];
    unsigned (*STs)[PQ] = (unsigned (*)[PQ])sm2;               // [m][d]
    unsigned (*qsb[2])[PQ];
    qsb[0] = (unsigned (*)[PQ])(sm2 + W_ST);
    qsb[1] = (unsigned (*)[PQ])(sm2 + W_ST + W_QS);
    float* ws   = (float*)(sm2 + W_ST + 2 * W_QS);
    float* dens = ws + 128;                                    // [2][128]

    int head = blockIdx.y;
    int sbase = blockIdx.x * SQT;
    int tid = threadIdx.x;
    int warp = tid >> 5, lane = tid & 31;
    int gid = lane >> 2, tig = lane & 3;
    int sw = (warp >> 2) * 32;
    int m0 = (warp & 3) * 32;
    int r4 = tid >> 2, c4 = (tid & 3) * 4;

    const float* qh  = qq + (size_t)head * Ss * Dd;
    const float* STg = g_ST + (size_t)head * Dd * Mm;

#pragma unroll
    for (int i = 0; i < 8; i++) {
        float4 t4 = *(const float4*)(STg + (size_t)r4 * Dd + c4 + i * 16);
        *(float4*)&STs[r4][c4 + i * 16] = t4;
    }
    if (tid < 128) ws[tid] = g_w2[head * Dd + tid];
    __syncthreads();

    {
        const float* qrow = qh + (size_t)(sbase + r4) * Dd;
        float4 qa[8];
#pragma unroll
        for (int i = 0; i < 8; i++)
            qa[i] = *(const float4*)(qrow + c4 + i * 16);
        float dsum = 0.f;
#pragma unroll
        for (int i = 0; i < 8; i++) {
            float p0 = phi(qa[i].x), p1 = phi(qa[i].y),
                  p2 = phi(qa[i].z), p3 = phi(qa[i].w);
            const float* wv = ws + c4 + i * 16;
            dsum += p0 * wv[0] + p1 * wv[1] + p2 * wv[2] + p3 * wv[3];
            uint4 st; st.x = f2tf(p0); st.y = f2tf(p1);
            st.z = f2tf(p2); st.w = f2tf(p3);
            *(uint4*)&qsb[0][r4][c4 + i * 16] = st;
        }
        dsum += __shfl_xor_sync(0xffffffffu, dsum, 1);
        dsum += __shfl_xor_sync(0xffffffffu, dsum, 2);
        if ((tid & 3) == 0) dens[r4] = dsum;
    }

    int sel = lane >> 3, lrow = lane & 7;
    unsigned aB[2];
#pragma unroll
    for (int b = 0; b < 2; b++)
        aB[b] = s2u(qsb[b]) +
            (((sw + (sel & 1) * 8 + lrow) * PQ + (sel >> 1) * 4) << 2);
    unsigned bB = s2u(STs) +
        (((m0 + (sel >> 1) * 8 + lrow) * PQ + (sel & 1) * 4) << 2);

    for (int c = 0; c < NCH; c++) {
        int cb = c & 1, nb = cb ^ 1;
        bool more = (c + 1 < NCH);

        float4 qn[8];
        if (more) {
            const float* qrow = qh + (size_t)(sbase + (c + 1) * 128 + r4) * Dd;
#pragma unroll
            for (int i = 0; i < 8; i++)
                qn[i] = *(const float4*)(qrow + c4 + i * 16);
        }
        __syncthreads();

        float acc[2][4][4];
#pragma unroll
        for (int ah = 0; ah < 2; ah++)
#pragma unroll
            for (int bi = 0; bi < 4; bi++)
#pragma unroll
                for (int t = 0; t < 4; t++) acc[ah][bi][t] = 0.f;
        float dsum = 0.f;

#pragma unroll
        for (int i = 0; i < 16; i++) {
            int k0 = i * 8;
            if (more && i >= 8) {
                int j = i - 8;
                float p0 = phi(qn[j].x), p1 = phi(qn[j].y),
                      p2 = phi(qn[j].z), p3 = phi(qn[j].w);
                const float* wv = ws + c4 + j * 16;
                dsum += p0 * wv[0] + p1 * wv[1] + p2 * wv[2] + p3 * wv[3];
                uint4 st; st.x = f2tf(p0); st.y = f2tf(p1);
                st.z = f2tf(p2); st.w = f2tf(p3);
                *(uint4*)&qsb[nb][r4][c4 + j * 16] = st;
            }
            unsigned A[2][4], B[2][4];
            ldsm4(A[0], aB[cb] + (k0 << 2));
            ldsm4(A[1], aB[cb] + ((16 * PQ + k0) << 2));
            ldsm4(B[0], bB + (k0 << 2));
            ldsm4(B[1], bB + ((16 * PQ + k0) << 2));
#pragma unroll
            for (int ah = 0; ah < 2; ah++)
#pragma unroll
                for (int bi = 0; bi < 4; bi++)
                    mma8(acc[ah][bi], A[ah], &B[bi >> 1][(bi & 1) * 2]);
        }
        if (more) {
            dsum += __shfl_xor_sync(0xffffffffu, dsum, 1);
            dsum += __shfl_xor_sync(0xffffffffu, dsum, 2);
            if ((tid & 3) == 0) dens[nb * 128 + r4] = dsum;
        }

        float* oh = out + ((size_t)head * Ss + sbase + c * 128) * Mm;
#pragma unroll
        for (int ah = 0; ah < 2; ah++) {
            int sr = sw + ah * 16 + gid;
            float inv0 = 1.f / (dens[cb * 128 + sr] + EPSV);
            float inv1 = 1.f / (dens[cb * 128 + sr + 8] + EPSV);
#pragma unroll
            for (int bi = 0; bi < 4; bi++) {
                int mc = m0 + bi * 8 + tig * 2;
                float2 r0 = make_float2(acc[ah][bi][0] * inv0, acc[ah][bi][1] * inv0);
                float2 r1 = make_float2(acc[ah][bi][2] * inv1, acc[ah][bi][3] * inv1);
                *(float2*)(oh + (size_t)sr * Mm + mc) = r0;
                *(float2*)(oh + (size_t)(sr + 8) * Mm + mc) = r1;
            }
        }
    }
}

// ---------------------------------------------------------------------------
extern "C" void kernel_launch(void* const* d_in, const int* in_sizes, int n_in,
                              void* d_out, int out_size) {
    (void)in_sizes; (void)n_in;
    const float* q      = (const float*)d_in[0];
    const float* k      = (const float*)d_in[1];
    const float* v      = (const float*)d_in[2];
    const float* mask   = (const float*)d_in[3];
    const float* S_prev = (const float*)d_in[4];
    const float* z_prev = (const float*)d_in[5];
    float* out = (float*)d_out;

    cudaFuncSetAttribute(k_phase1, cudaFuncAttributeMaxDynamicSharedMemorySize,
                         P1_SMEM_BYTES);
    cudaFuncSetAttribute(k_phase2, cudaFuncAttributeMaxDynamicSharedMemorySize,
                         SM2_BYTES);

    const long N_OUT = (long)BH * Ss * Mm;
    const long N_ST  = (long)BH * Dd * Mm;
    const long N_ZT  = (long)BH * Dd * Ss;
    long osz = (long)out_size;
    float* ztp  = (osz >= N_OUT + N_ST + N_ZT) ? (out + N_OUT + N_ST) : (float*)0;
    float* outS = (osz >= N_OUT + N_ST) ? (out + N_OUT) : (float*)0;

    dim3 g1(Ss / P1_CHUNK, BH);
    k_phase1<<<g1, 512, P1_SMEM_BYTES>>>(k, v, mask, z_prev, ztp);

    dim3 gt(Dd / 32, Mm / 32, BH);
    k_transS<<<gt, dim3(32, 8)>>>(S_prev, z_prev, outS);

    dim3 g2(Ss / SQT, BH);
    k_phase2<<<g2, 512, SM2_BYTES>>>(q, out);
}